// round 2
// baseline (speedup 1.0000x reference)
#include <cuda_runtime.h>
#include <cstdint>

// ---------------- problem constants ----------------
#define B_    4
#define QL_   1024
#define CL_   3072
#define KL_   4096      // CL + QL
#define H_    2048
#define NH_   16
#define NKV_  4
#define HD_   128
#define GROUPS_ 4       // NH / NKV

__device__ __constant__ float d_dummy; // keep nvcc happy about constant usage

constexpr float EPS_   = 1e-6f;
constexpr float SCALE_ = 0.08838834764831845f; // 128^-0.5

// ---------------- scratch (device globals; no allocations allowed) ----------------
__device__ float g_qraw[(size_t)B_ * QL_ * NH_ * HD_];   // [B*QL, NH*HD]
__device__ float g_kraw[(size_t)B_ * KL_ * NKV_ * HD_];  // [B*KL, NKV*HD]
__device__ float g_vraw[(size_t)B_ * KL_ * NKV_ * HD_];  // [B*KL, NKV*HD]
__device__ float g_qn  [(size_t)B_ * NH_ * QL_ * HD_];   // [B, NH, QL, HD]
__device__ float g_kn  [(size_t)B_ * NKV_ * KL_ * HD_];  // [B, NKV, KL, HD]
__device__ float g_ao  [(size_t)B_ * QL_ * NH_ * HD_];   // [B*QL, NH*HD]

// ---------------- generic fp32 GEMM: C[M,N] = A[M,2048] @ W[2048,N] ----------------
// 128x128 block, 16-deep K tiles, 8x8 per-thread micro-tile, 256 threads.
// CONCAT mode: A rows come from concat(ctx, noise) along sequence per batch.

template <bool CONCAT>
__device__ __forceinline__ const float* a_rowptr(const float* __restrict__ A,
                                                 const float* __restrict__ ctx,
                                                 const float* __restrict__ noise,
                                                 int r) {
    if (!CONCAT) return A + (size_t)r * H_;
    int b = r >> 12;        // / KL_
    int p = r & (KL_ - 1);  // % KL_
    return (p < CL_) ? ctx + (size_t)(b * CL_ + p) * H_
                     : noise + (size_t)(b * QL_ + (p - CL_)) * H_;
}

template <bool CONCAT>
__global__ __launch_bounds__(256) void gemm128_kernel(
    const float* __restrict__ A, const float* __restrict__ ctx,
    const float* __restrict__ noise, const float* __restrict__ W,
    float* __restrict__ C, int M, int N) {
    __shared__ float As[16][128];
    __shared__ float Bs[16][128];

    const int tid  = threadIdx.x;
    const int row0 = blockIdx.y * 128;
    const int col0 = blockIdx.x * 128;
    const int tx   = tid & 15;
    const int ty   = tid >> 4;

    // A-tile load mapping: float4 id f in {tid, tid+256}: m = f>>2, k = (f&3)*4
    const int m0 = tid >> 2;
    const int ka = (tid & 3) * 4;
    // W-tile load mapping: f: k = f>>5, n = (f&31)*4 ; second at k+8
    const int kb = tid >> 5;
    const int nb = (tid & 31) * 4;

    const float* ar0 = a_rowptr<CONCAT>(A, ctx, noise, row0 + m0);
    const float* ar1 = a_rowptr<CONCAT>(A, ctx, noise, row0 + m0 + 64);

    float acc[8][8];
#pragma unroll
    for (int i = 0; i < 8; i++)
#pragma unroll
        for (int j = 0; j < 8; j++) acc[i][j] = 0.0f;

    for (int k0 = 0; k0 < H_; k0 += 16) {
        float4 a0 = *(const float4*)(ar0 + k0 + ka);
        float4 a1 = *(const float4*)(ar1 + k0 + ka);
        float4 b0 = *(const float4*)(W + (size_t)(k0 + kb) * N + col0 + nb);
        float4 b1 = *(const float4*)(W + (size_t)(k0 + kb + 8) * N + col0 + nb);

        __syncthreads();
        As[ka + 0][m0] = a0.x; As[ka + 1][m0] = a0.y;
        As[ka + 2][m0] = a0.z; As[ka + 3][m0] = a0.w;
        As[ka + 0][m0 + 64] = a1.x; As[ka + 1][m0 + 64] = a1.y;
        As[ka + 2][m0 + 64] = a1.z; As[ka + 3][m0 + 64] = a1.w;
        *(float4*)&Bs[kb][nb]     = b0;
        *(float4*)&Bs[kb + 8][nb] = b1;
        __syncthreads();

#pragma unroll
        for (int kk = 0; kk < 16; kk++) {
            float4 av0 = *(const float4*)&As[kk][ty * 8];
            float4 av1 = *(const float4*)&As[kk][ty * 8 + 4];
            float4 bv0 = *(const float4*)&Bs[kk][tx * 8];
            float4 bv1 = *(const float4*)&Bs[kk][tx * 8 + 4];
            float a[8] = {av0.x, av0.y, av0.z, av0.w, av1.x, av1.y, av1.z, av1.w};
            float b[8] = {bv0.x, bv0.y, bv0.z, bv0.w, bv1.x, bv1.y, bv1.z, bv1.w};
#pragma unroll
            for (int i = 0; i < 8; i++)
#pragma unroll
                for (int j = 0; j < 8; j++) acc[i][j] += a[i] * b[j];
        }
    }

#pragma unroll
    for (int i = 0; i < 8; i++) {
        float* crow = C + (size_t)(row0 + ty * 8 + i) * N + col0 + tx * 8;
        *(float4*)(crow)     = make_float4(acc[i][0], acc[i][1], acc[i][2], acc[i][3]);
        *(float4*)(crow + 4) = make_float4(acc[i][4], acc[i][5], acc[i][6], acc[i][7]);
    }
}

// ---------------- RMSNorm + RoPE ----------------
__device__ __forceinline__ float block_sum128(float v, float* red) {
#pragma unroll
    for (int o = 16; o; o >>= 1) v += __shfl_xor_sync(0xffffffffu, v, o);
    if ((threadIdx.x & 31) == 0) red[threadIdx.x >> 5] = v;
    __syncthreads();
    return red[0] + red[1] + red[2] + red[3];
}

// Q: in [B*QL, NH*HD] -> norm+rope -> out [B, NH, QL, HD]; pos = CL + q
__global__ __launch_bounds__(128) void qnorm_rope_kernel(
    const float* __restrict__ qraw, const float* __restrict__ cosT,
    const float* __restrict__ sinT, const float* __restrict__ w,
    float* __restrict__ qout) {
    __shared__ float red[4];
    __shared__ float sx[128];
    const int blk = blockIdx.x;           // 0 .. B*QL*NH-1
    const int h   = blk & (NH_ - 1);
    const int row = blk >> 4;             // b*QL + q
    const int b   = row >> 10;
    const int qi  = row & (QL_ - 1);
    const int t   = threadIdx.x;

    float x = qraw[(size_t)row * (NH_ * HD_) + h * HD_ + t];
    float ss = block_sum128(x * x, red);
    float inv = rsqrtf(ss * (1.0f / HD_) + EPS_);
    float xn = x * inv * w[t];
    sx[t] = xn;
    __syncthreads();
    float rot = (t < 64) ? -sx[t + 64] : sx[t - 64];
    int pos = CL_ + qi;
    size_t ci = ((size_t)b * KL_ + pos) * HD_ + t;
    float outv = xn * cosT[ci] + rot * sinT[ci];
    qout[(((size_t)(b * NH_ + h) * QL_) + qi) * HD_ + t] = outv;
}

// K: in [B*KL, NKV*HD] -> norm+rope -> out [B, NKV, KL, HD]; pos = p
__global__ __launch_bounds__(128) void knorm_rope_kernel(
    const float* __restrict__ kraw, const float* __restrict__ cosT,
    const float* __restrict__ sinT, const float* __restrict__ w,
    float* __restrict__ kout) {
    __shared__ float red[4];
    __shared__ float sx[128];
    const int blk = blockIdx.x;           // 0 .. B*KL*NKV-1
    const int kvh = blk & (NKV_ - 1);
    const int row = blk >> 2;             // b*KL + p
    const int b   = row >> 12;
    const int p   = row & (KL_ - 1);
    const int t   = threadIdx.x;

    float x = kraw[(size_t)row * (NKV_ * HD_) + kvh * HD_ + t];
    float ss = block_sum128(x * x, red);
    float inv = rsqrtf(ss * (1.0f / HD_) + EPS_);
    float xn = x * inv * w[t];
    sx[t] = xn;
    __syncthreads();
    float rot = (t < 64) ? -sx[t + 64] : sx[t - 64];
    size_t ci = ((size_t)b * KL_ + p) * HD_ + t;
    float outv = xn * cosT[ci] + rot * sinT[ci];
    kout[(((size_t)(b * NKV_ + kvh) * KL_) + p) * HD_ + t] = outv;
}

// ---------------- flash attention ----------------
// 64 queries x 64 keys per tile, 256 threads (tx 0..15, ty 0..15).
// Each thread: 4 q rows (ty*4+i), 4 k cols (tx + 16*j), output d = (tx + 16*jj)*4 + c.
// K/V smem rows padded to 33 float4 (132 floats) to spread bank groups.
constexpr int ROWF4 = 33;
constexpr int FLASH_SMEM = (3 * 64 * ROWF4 * 4 + 64 * 64) * 4; // 117760 bytes

__global__ __launch_bounds__(256) void flash_kernel(
    const float* __restrict__ q, const float* __restrict__ k,
    const float* __restrict__ vraw, float* __restrict__ o) {
    extern __shared__ float sm[];
    float4* Q4 = (float4*)sm;
    float4* K4 = Q4 + 64 * ROWF4;
    float4* V4 = K4 + 64 * ROWF4;
    float*  Ps = (float*)(V4 + 64 * ROWF4);

    const int b   = blockIdx.z;
    const int h   = blockIdx.y;
    const int q0  = blockIdx.x * 64;
    const int kvh = h >> 2;  // GROUPS=4
    const int tid = threadIdx.x;
    const int tx  = tid & 15;
    const int ty  = tid >> 4;

    // load Q tile [64,128]
    const float4* qsrc = (const float4*)(q + (((size_t)(b * NH_ + h) * QL_ + q0) * HD_));
    for (int i = tid; i < 2048; i += 256) {
        int r = i >> 5, d4 = i & 31;
        Q4[r * ROWF4 + d4] = qsrc[i];
    }

    float mrow[4], lrow[4], acc[4][8];
#pragma unroll
    for (int i = 0; i < 4; i++) {
        mrow[i] = -3.0e38f;
        lrow[i] = 0.0f;
#pragma unroll
        for (int j = 0; j < 8; j++) acc[i][j] = 0.0f;
    }

    const float4* ksrc = (const float4*)(k + ((size_t)(b * NKV_ + kvh) * KL_) * HD_);

    for (int k0 = 0; k0 < KL_; k0 += 64) {
        __syncthreads();  // previous tile fully consumed (also covers Q load, 1st iter)
        for (int i = tid; i < 2048; i += 256) {
            int r = i >> 5, d4 = i & 31;
            K4[r * ROWF4 + d4] = ksrc[(size_t)k0 * 32 + i];
            V4[r * ROWF4 + d4] =
                ((const float4*)vraw)[((size_t)(b * KL_ + k0 + r)) * 128 + kvh * 32 + d4];
        }
        __syncthreads();

        // scores: S[i][j], q = ty*4+i, key = tx + 16*j
        float S[4][4] = {{0,0,0,0},{0,0,0,0},{0,0,0,0},{0,0,0,0}};
#pragma unroll
        for (int d4 = 0; d4 < 32; d4++) {
            float4 a0 = Q4[(ty * 4 + 0) * ROWF4 + d4];
            float4 a1 = Q4[(ty * 4 + 1) * ROWF4 + d4];
            float4 a2 = Q4[(ty * 4 + 2) * ROWF4 + d4];
            float4 a3 = Q4[(ty * 4 + 3) * ROWF4 + d4];
            float4 b0 = K4[(tx +  0) * ROWF4 + d4];
            float4 b1 = K4[(tx + 16) * ROWF4 + d4];
            float4 b2 = K4[(tx + 32) * ROWF4 + d4];
            float4 b3 = K4[(tx + 48) * ROWF4 + d4];
#define DOT4(S_, A_, B_) S_ += A_.x * B_.x + A_.y * B_.y + A_.z * B_.z + A_.w * B_.w
            DOT4(S[0][0], a0, b0); DOT4(S[0][1], a0, b1); DOT4(S[0][2], a0, b2); DOT4(S[0][3], a0, b3);
            DOT4(S[1][0], a1, b0); DOT4(S[1][1], a1, b1); DOT4(S[1][2], a1, b2); DOT4(S[1][3], a1, b3);
            DOT4(S[2][0], a2, b0); DOT4(S[2][1], a2, b1); DOT4(S[2][2], a2, b2); DOT4(S[2][3], a2, b3);
            DOT4(S[3][0], a3, b0); DOT4(S[3][1], a3, b1); DOT4(S[3][2], a3, b2); DOT4(S[3][3], a3, b3);
#undef DOT4
        }

        // online softmax per q row; reductions across tx live in half-warps (xor<=8)
#pragma unroll
        for (int i = 0; i < 4; i++) {
            float s0 = S[i][0] * SCALE_, s1 = S[i][1] * SCALE_;
            float s2 = S[i][2] * SCALE_, s3 = S[i][3] * SCALE_;
            float mx = fmaxf(fmaxf(s0, s1), fmaxf(s2, s3));
#pragma unroll
            for (int o2 = 8; o2; o2 >>= 1)
                mx = fmaxf(mx, __shfl_xor_sync(0xffffffffu, mx, o2));
            float mnew = fmaxf(mrow[i], mx);
            float corr = __expf(mrow[i] - mnew);
            mrow[i] = mnew;
            float p0 = __expf(s0 - mnew), p1 = __expf(s1 - mnew);
            float p2 = __expf(s2 - mnew), p3 = __expf(s3 - mnew);
            float rs = p0 + p1 + p2 + p3;
#pragma unroll
            for (int o2 = 8; o2; o2 >>= 1)
                rs += __shfl_xor_sync(0xffffffffu, rs, o2);
            lrow[i] = lrow[i] * corr + rs;
#pragma unroll
            for (int j = 0; j < 8; j++) acc[i][j] *= corr;
            Ps[(ty * 4 + i) * 64 + tx +  0] = p0;
            Ps[(ty * 4 + i) * 64 + tx + 16] = p1;
            Ps[(ty * 4 + i) * 64 + tx + 32] = p2;
            Ps[(ty * 4 + i) * 64 + tx + 48] = p3;
        }
        __syncthreads();

        // PV: O[q][d] += sum_k P[q][k] * V[k][d]
#pragma unroll 4
        for (int kk = 0; kk < 64; kk++) {
            float4 v0 = V4[kk * ROWF4 + tx];
            float4 v1 = V4[kk * ROWF4 + tx + 16];
            float p0 = Ps[(ty * 4 + 0) * 64 + kk];
            float p1 = Ps[(ty * 4 + 1) * 64 + kk];
            float p2 = Ps[(ty * 4 + 2) * 64 + kk];
            float p3 = Ps[(ty * 4 + 3) * 64 + kk];
            acc[0][0] += p0 * v0.x; acc[0][1] += p0 * v0.y; acc[0][2] += p0 * v0.z; acc[0][3] += p0 * v0.w;
            acc[0][4] += p0 * v1.x; acc[0][5] += p0 * v1.y; acc[0][6] += p0 * v1.z; acc[0][7] += p0 * v1.w;
            acc[1][0] += p1 * v0.x; acc[1][1] += p1 * v0.y; acc[1][2] += p1 * v0.z; acc[1][3] += p1 * v0.w;
            acc[1][4] += p1 * v1.x; acc[1][5] += p1 * v1.y; acc[1][6] += p1 * v1.z; acc[1][7] += p1 * v1.w;
            acc[2][0] += p2 * v0.x; acc[2][1] += p2 * v0.y; acc[2][2] += p2 * v0.z; acc[2][3] += p2 * v0.w;
            acc[2][4] += p2 * v1.x; acc[2][5] += p2 * v1.y; acc[2][6] += p2 * v1.z; acc[2][7] += p2 * v1.w;
            acc[3][0] += p3 * v0.x; acc[3][1] += p3 * v0.y; acc[3][2] += p3 * v0.z; acc[3][3] += p3 * v0.w;
            acc[3][4] += p3 * v1.x; acc[3][5] += p3 * v1.y; acc[3][6] += p3 * v1.z; acc[3][7] += p3 * v1.w;
        }
    }

    // epilogue: O /= l, write [B*QL, NH*HD]
#pragma unroll
    for (int i = 0; i < 4; i++) {
        float inv = 1.0f / lrow[i];
        float* orow = o + ((size_t)(b * QL_ + q0 + ty * 4 + i)) * (NH_ * HD_) + h * HD_;
        ((float4*)orow)[tx] =
            make_float4(acc[i][0] * inv, acc[i][1] * inv, acc[i][2] * inv, acc[i][3] * inv);
        ((float4*)orow)[tx + 16] =
            make_float4(acc[i][4] * inv, acc[i][5] * inv, acc[i][6] * inv, acc[i][7] * inv);
    }
}

// ---------------- launch ----------------
extern "C" void kernel_launch(void* const* d_in, const int* in_sizes, int n_in,
                              void* d_out, int out_size) {
    const float* noise = (const float*)d_in[0];
    const float* ctx   = (const float*)d_in[1];
    const float* cosT  = (const float*)d_in[2];
    const float* sinT  = (const float*)d_in[3];
    const float* Wq    = (const float*)d_in[4];
    const float* Wk    = (const float*)d_in[5];
    const float* Wv    = (const float*)d_in[6];
    const float* Wo    = (const float*)d_in[7];
    const float* qnw   = (const float*)d_in[8];
    const float* knw   = (const float*)d_in[9];
    float* out = (float*)d_out;

    float *qraw, *kraw, *vraw, *qn, *kn, *ao;
    cudaGetSymbolAddress((void**)&qraw, g_qraw);
    cudaGetSymbolAddress((void**)&kraw, g_kraw);
    cudaGetSymbolAddress((void**)&vraw, g_vraw);
    cudaGetSymbolAddress((void**)&qn,   g_qn);
    cudaGetSymbolAddress((void**)&kn,   g_kn);
    cudaGetSymbolAddress((void**)&ao,   g_ao);

    cudaFuncSetAttribute(flash_kernel, cudaFuncAttributeMaxDynamicSharedMemorySize,
                         FLASH_SMEM);

    // projections
    gemm128_kernel<false><<<dim3(16, 32), 256>>>(noise, nullptr, nullptr, Wq, qraw,
                                                 B_ * QL_, NH_ * HD_);
    gemm128_kernel<true><<<dim3(4, 128), 256>>>(nullptr, ctx, noise, Wk, kraw,
                                                B_ * KL_, NKV_ * HD_);
    gemm128_kernel<true><<<dim3(4, 128), 256>>>(nullptr, ctx, noise, Wv, vraw,
                                                B_ * KL_, NKV_ * HD_);
    // norm + rope
    qnorm_rope_kernel<<<B_ * QL_ * NH_, 128>>>(qraw, cosT, sinT, qnw, qn);
    knorm_rope_kernel<<<B_ * KL_ * NKV_, 128>>>(kraw, cosT, sinT, knw, kn);
    // attention
    flash_kernel<<<dim3(QL_ / 64, NH_, B_), 256, FLASH_SMEM>>>(qn, kn, vraw, ao);
    // output projection
    gemm128_kernel<false><<<dim3(16, 32), 256>>>(ao, nullptr, nullptr, Wo, out,
                                                 B_ * QL_, NH_ * HD_);
}

// round 5
// speedup vs baseline: 1.6638x; 1.6638x over previous
#include <cuda_runtime.h>
#include <cstdint>

// ---------------- problem constants ----------------
#define B_    4
#define QL_   1024
#define CL_   3072
#define KL_   4096      // CL + QL
#define H_    2048
#define NH_   16
#define NKV_  4
#define HD_   128
#define GROUPS_ 4       // NH / NKV

constexpr float EPS_   = 1e-6f;
constexpr float SCALE_ = 0.08838834764831845f; // 128^-0.5

// ---------------- scratch (device globals; no allocations allowed) ----------------
__device__ float g_qraw[(size_t)B_ * QL_ * NH_ * HD_];   // [B*QL, NH*HD]
__device__ float g_kraw[(size_t)B_ * KL_ * NKV_ * HD_];  // [B*KL, NKV*HD]
__device__ float g_vraw[(size_t)B_ * KL_ * NKV_ * HD_];  // [B*KL, NKV*HD]
__device__ float g_qn  [(size_t)B_ * NH_ * QL_ * HD_];   // [B, NH, QL, HD]
__device__ float g_kn  [(size_t)B_ * NKV_ * KL_ * HD_];  // [B, NKV, KL, HD]
__device__ float g_ao  [(size_t)B_ * QL_ * NH_ * HD_];   // [B*QL, NH*HD]

// ---------------- helpers ----------------
template <bool CONCAT>
__device__ __forceinline__ const float* a_rowptr(const float* __restrict__ A,
                                                 const float* __restrict__ ctx,
                                                 const float* __restrict__ noise,
                                                 int r) {
    if (!CONCAT) return A + (size_t)r * H_;
    int b = r >> 12;        // / KL_
    int p = r & (KL_ - 1);  // % KL_
    return (p < CL_) ? ctx + (size_t)(b * CL_ + p) * H_
                     : noise + (size_t)(b * QL_ + (p - CL_)) * H_;
}

__device__ __forceinline__ uint32_t f2tf32(float x) {
    uint32_t r;
    asm("cvt.rna.tf32.f32 %0, %1;" : "=r"(r) : "f"(x));
    return r;
}

__device__ __forceinline__ void mma_tf32(float* c, const uint32_t* a, const uint32_t* b) {
    asm volatile(
        "mma.sync.aligned.m16n8k8.row.col.f32.tf32.tf32.f32 "
        "{%0,%1,%2,%3}, {%4,%5,%6,%7}, {%8,%9}, {%0,%1,%2,%3};\n"
        : "+f"(c[0]), "+f"(c[1]), "+f"(c[2]), "+f"(c[3])
        : "r"(a[0]), "r"(a[1]), "r"(a[2]), "r"(a[3]), "r"(b[0]), "r"(b[1]));
}

// ---------------- tf32 tensor-core GEMM (3xTF32 split => ~fp32 accuracy) ----------------
// C[M,N] = A[M,2048] @ W[2048,N].  Block tile 128x128, kTile 32, 256 threads (8 warps).
// Warp grid 4(m) x 2(n): warp tile 32x64 = 2 m-tiles x 8 n-tiles of m16n8k8.
// A smem [m][k] pad 36; B smem [k][n] pad 132 (both conflict-free fragment loads).

#define APAD 36
#define BPAD 132

template <bool CONCAT>
__global__ __launch_bounds__(256) void gemm_tf32_kernel(
    const float* __restrict__ A, const float* __restrict__ ctx,
    const float* __restrict__ noise, const float* __restrict__ W,
    float* __restrict__ C, int M, int N) {
    __shared__ float As[128 * APAD];
    __shared__ float Bs[32 * BPAD];

    const int tid  = threadIdx.x;
    const int lane = tid & 31;
    const int wid  = tid >> 5;
    const int warp_m = wid & 3;   // 0..3 -> m offset *32
    const int warp_n = wid >> 2;  // 0..1 -> n offset *64

    const int row0 = blockIdx.y * 128;
    const int col0 = blockIdx.x * 128;

    // global->smem load mapping
    const int ka = (tid & 7) * 4;        // A: k offset within tile (float4)
    const int ar = tid >> 3;             // A: base row (0..31), rows ar+32*i
    const int nb = (tid & 31) * 4;       // B: n offset
    const int kb = tid >> 5;             // B: base k row (0..7), rows kb+8*i

    const float* arow[4];
#pragma unroll
    for (int i = 0; i < 4; i++)
        arow[i] = a_rowptr<CONCAT>(A, ctx, noise, row0 + ar + 32 * i);

    const int l4 = lane >> 2;   // 0..7
    const int lk = lane & 3;    // 0..3

    float acc[2][8][4];
#pragma unroll
    for (int mt = 0; mt < 2; mt++)
#pragma unroll
        for (int nt = 0; nt < 8; nt++)
#pragma unroll
            for (int c = 0; c < 4; c++) acc[mt][nt][c] = 0.0f;

    for (int k0 = 0; k0 < H_; k0 += 32) {
        float4 areg[4], breg[4];
#pragma unroll
        for (int i = 0; i < 4; i++)
            areg[i] = *(const float4*)(arow[i] + k0 + ka);
#pragma unroll
        for (int i = 0; i < 4; i++)
            breg[i] = *(const float4*)(W + (size_t)(k0 + kb + 8 * i) * N + col0 + nb);

        __syncthreads();
#pragma unroll
        for (int i = 0; i < 4; i++)
            *(float4*)&As[(ar + 32 * i) * APAD + ka] = areg[i];
#pragma unroll
        for (int i = 0; i < 4; i++)
            *(float4*)&Bs[(kb + 8 * i) * BPAD + nb] = breg[i];
        __syncthreads();

#pragma unroll
        for (int kk = 0; kk < 32; kk += 8) {
            // load + split A fragments (2 m-tiles)
            uint32_t ahi[2][4], alo[2][4];
#pragma unroll
            for (int mt = 0; mt < 2; mt++) {
                int r0 = (warp_m * 32 + mt * 16 + l4) * APAD;
                int r1 = r0 + 8 * APAD;
                float f0 = As[r0 + kk + lk];
                float f1 = As[r1 + kk + lk];
                float f2 = As[r0 + kk + lk + 4];
                float f3 = As[r1 + kk + lk + 4];
                ahi[mt][0] = f2tf32(f0); alo[mt][0] = f2tf32(f0 - __uint_as_float(ahi[mt][0]));
                ahi[mt][1] = f2tf32(f1); alo[mt][1] = f2tf32(f1 - __uint_as_float(ahi[mt][1]));
                ahi[mt][2] = f2tf32(f2); alo[mt][2] = f2tf32(f2 - __uint_as_float(ahi[mt][2]));
                ahi[mt][3] = f2tf32(f3); alo[mt][3] = f2tf32(f3 - __uint_as_float(ahi[mt][3]));
            }
            // load + split B fragments (8 n-tiles)
            uint32_t bhi[8][2], blo[8][2];
#pragma unroll
            for (int nt = 0; nt < 8; nt++) {
                int cn = warp_n * 64 + nt * 8 + l4;
                float g0 = Bs[(kk + lk) * BPAD + cn];
                float g1 = Bs[(kk + lk + 4) * BPAD + cn];
                bhi[nt][0] = f2tf32(g0); blo[nt][0] = f2tf32(g0 - __uint_as_float(bhi[nt][0]));
                bhi[nt][1] = f2tf32(g1); blo[nt][1] = f2tf32(g1 - __uint_as_float(bhi[nt][1]));
            }
#pragma unroll
            for (int mt = 0; mt < 2; mt++)
#pragma unroll
                for (int nt = 0; nt < 8; nt++) {
                    mma_tf32(acc[mt][nt], ahi[mt], bhi[nt]);
                    mma_tf32(acc[mt][nt], ahi[mt], blo[nt]);
                    mma_tf32(acc[mt][nt], alo[mt], bhi[nt]);
                }
        }
    }

    // epilogue
#pragma unroll
    for (int mt = 0; mt < 2; mt++) {
        int r0 = row0 + warp_m * 32 + mt * 16 + l4;
#pragma unroll
        for (int nt = 0; nt < 8; nt++) {
            int cn = col0 + warp_n * 64 + nt * 8 + 2 * lk;
            *(float2*)(C + (size_t)r0 * N + cn) = make_float2(acc[mt][nt][0], acc[mt][nt][1]);
            *(float2*)(C + (size_t)(r0 + 8) * N + cn) = make_float2(acc[mt][nt][2], acc[mt][nt][3]);
        }
    }
}

// ---------------- RMSNorm + RoPE ----------------
__device__ __forceinline__ float block_sum128(float v, float* red) {
#pragma unroll
    for (int o = 16; o; o >>= 1) v += __shfl_xor_sync(0xffffffffu, v, o);
    if ((threadIdx.x & 31) == 0) red[threadIdx.x >> 5] = v;
    __syncthreads();
    return red[0] + red[1] + red[2] + red[3];
}

__global__ __launch_bounds__(128) void qnorm_rope_kernel(
    const float* __restrict__ qraw, const float* __restrict__ cosT,
    const float* __restrict__ sinT, const float* __restrict__ w,
    float* __restrict__ qout) {
    __shared__ float red[4];
    __shared__ float sx[128];
    const int blk = blockIdx.x;
    const int h   = blk & (NH_ - 1);
    const int row = blk >> 4;
    const int b   = row >> 10;
    const int qi  = row & (QL_ - 1);
    const int t   = threadIdx.x;

    float x = qraw[(size_t)row * (NH_ * HD_) + h * HD_ + t];
    float ss = block_sum128(x * x, red);
    float inv = rsqrtf(ss * (1.0f / HD_) + EPS_);
    float xn = x * inv * w[t];
    sx[t] = xn;
    __syncthreads();
    float rot = (t < 64) ? -sx[t + 64] : sx[t - 64];
    int pos = CL_ + qi;
    size_t ci = ((size_t)b * KL_ + pos) * HD_ + t;
    float outv = xn * cosT[ci] + rot * sinT[ci];
    qout[(((size_t)(b * NH_ + h) * QL_) + qi) * HD_ + t] = outv;
}

__global__ __launch_bounds__(128) void knorm_rope_kernel(
    const float* __restrict__ kraw, const float* __restrict__ cosT,
    const float* __restrict__ sinT, const float* __restrict__ w,
    float* __restrict__ kout) {
    __shared__ float red[4];
    __shared__ float sx[128];
    const int blk = blockIdx.x;
    const int kvh = blk & (NKV_ - 1);
    const int row = blk >> 2;
    const int b   = row >> 12;
    const int p   = row & (KL_ - 1);
    const int t   = threadIdx.x;

    float x = kraw[(size_t)row * (NKV_ * HD_) + kvh * HD_ + t];
    float ss = block_sum128(x * x, red);
    float inv = rsqrtf(ss * (1.0f / HD_) + EPS_);
    float xn = x * inv * w[t];
    sx[t] = xn;
    __syncthreads();
    float rot = (t < 64) ? -sx[t + 64] : sx[t - 64];
    size_t ci = ((size_t)b * KL_ + p) * HD_ + t;
    float outv = xn * cosT[ci] + rot * sinT[ci];
    kout[(((size_t)(b * NKV_ + kvh) * KL_) + p) * HD_ + t] = outv;
}

// ---------------- flash attention (fp32 SIMT — unchanged this round) ----------------
constexpr int ROWF4 = 33;
constexpr int FLASH_SMEM = (3 * 64 * ROWF4 * 4 + 64 * 64) * 4; // 117760 bytes

__global__ __launch_bounds__(256) void flash_kernel(
    const float* __restrict__ q, const float* __restrict__ k,
    const float* __restrict__ vraw, float* __restrict__ o) {
    extern __shared__ float sm[];
    float4* Q4 = (float4*)sm;
    float4* K4 = Q4 + 64 * ROWF4;
    float4* V4 = K4 + 64 * ROWF4;
    float*  Ps = (float*)(V4 + 64 * ROWF4);

    const int b   = blockIdx.z;
    const int h   = blockIdx.y;
    const int q0  = blockIdx.x * 64;
    const int kvh = h >> 2;
    const int tid = threadIdx.x;
    const int tx  = tid & 15;
    const int ty  = tid >> 4;

    const float4* qsrc = (const float4*)(q + (((size_t)(b * NH_ + h) * QL_ + q0) * HD_));
    for (int i = tid; i < 2048; i += 256) {
        int r = i >> 5, d4 = i & 31;
        Q4[r * ROWF4 + d4] = qsrc[i];
    }

    float mrow[4], lrow[4], acc[4][8];
#pragma unroll
    for (int i = 0; i < 4; i++) {
        mrow[i] = -3.0e38f;
        lrow[i] = 0.0f;
#pragma unroll
        for (int j = 0; j < 8; j++) acc[i][j] = 0.0f;
    }

    const float4* ksrc = (const float4*)(k + ((size_t)(b * NKV_ + kvh) * KL_) * HD_);

    for (int k0 = 0; k0 < KL_; k0 += 64) {
        __syncthreads();
        for (int i = tid; i < 2048; i += 256) {
            int r = i >> 5, d4 = i & 31;
            K4[r * ROWF4 + d4] = ksrc[(size_t)k0 * 32 + i];
            V4[r * ROWF4 + d4] =
                ((const float4*)vraw)[((size_t)(b * KL_ + k0 + r)) * 128 + kvh * 32 + d4];
        }
        __syncthreads();

        float S[4][4] = {{0,0,0,0},{0,0,0,0},{0,0,0,0},{0,0,0,0}};
#pragma unroll
        for (int d4 = 0; d4 < 32; d4++) {
            float4 a0 = Q4[(ty * 4 + 0) * ROWF4 + d4];
            float4 a1 = Q4[(ty * 4 + 1) * ROWF4 + d4];
            float4 a2 = Q4[(ty * 4 + 2) * ROWF4 + d4];
            float4 a3 = Q4[(ty * 4 + 3) * ROWF4 + d4];
            float4 b0 = K4[(tx +  0) * ROWF4 + d4];
            float4 b1 = K4[(tx + 16) * ROWF4 + d4];
            float4 b2 = K4[(tx + 32) * ROWF4 + d4];
            float4 b3 = K4[(tx + 48) * ROWF4 + d4];
#define DOT4(S_, A_, B_) S_ += A_.x * B_.x + A_.y * B_.y + A_.z * B_.z + A_.w * B_.w
            DOT4(S[0][0], a0, b0); DOT4(S[0][1], a0, b1); DOT4(S[0][2], a0, b2); DOT4(S[0][3], a0, b3);
            DOT4(S[1][0], a1, b0); DOT4(S[1][1], a1, b1); DOT4(S[1][2], a1, b2); DOT4(S[1][3], a1, b3);
            DOT4(S[2][0], a2, b0); DOT4(S[2][1], a2, b1); DOT4(S[2][2], a2, b2); DOT4(S[2][3], a2, b3);
            DOT4(S[3][0], a3, b0); DOT4(S[3][1], a3, b1); DOT4(S[3][2], a3, b2); DOT4(S[3][3], a3, b3);
#undef DOT4
        }

#pragma unroll
        for (int i = 0; i < 4; i++) {
            float s0 = S[i][0] * SCALE_, s1 = S[i][1] * SCALE_;
            float s2 = S[i][2] * SCALE_, s3 = S[i][3] * SCALE_;
            float mx = fmaxf(fmaxf(s0, s1), fmaxf(s2, s3));
#pragma unroll
            for (int o2 = 8; o2; o2 >>= 1)
                mx = fmaxf(mx, __shfl_xor_sync(0xffffffffu, mx, o2));
            float mnew = fmaxf(mrow[i], mx);
            float corr = __expf(mrow[i] - mnew);
            mrow[i] = mnew;
            float p0 = __expf(s0 - mnew), p1 = __expf(s1 - mnew);
            float p2 = __expf(s2 - mnew), p3 = __expf(s3 - mnew);
            float rs = p0 + p1 + p2 + p3;
#pragma unroll
            for (int o2 = 8; o2; o2 >>= 1)
                rs += __shfl_xor_sync(0xffffffffu, rs, o2);
            lrow[i] = lrow[i] * corr + rs;
#pragma unroll
            for (int j = 0; j < 8; j++) acc[i][j] *= corr;
            Ps[(ty * 4 + i) * 64 + tx +  0] = p0;
            Ps[(ty * 4 + i) * 64 + tx + 16] = p1;
            Ps[(ty * 4 + i) * 64 + tx + 32] = p2;
            Ps[(ty * 4 + i) * 64 + tx + 48] = p3;
        }
        __syncthreads();

#pragma unroll 4
        for (int kk = 0; kk < 64; kk++) {
            float4 v0 = V4[kk * ROWF4 + tx];
            float4 v1 = V4[kk * ROWF4 + tx + 16];
            float p0 = Ps[(ty * 4 + 0) * 64 + kk];
            float p1 = Ps[(ty * 4 + 1) * 64 + kk];
            float p2 = Ps[(ty * 4 + 2) * 64 + kk];
            float p3 = Ps[(ty * 4 + 3) * 64 + kk];
            acc[0][0] += p0 * v0.x; acc[0][1] += p0 * v0.y; acc[0][2] += p0 * v0.z; acc[0][3] += p0 * v0.w;
            acc[0][4] += p0 * v1.x; acc[0][5] += p0 * v1.y; acc[0][6] += p0 * v1.z; acc[0][7] += p0 * v1.w;
            acc[1][0] += p1 * v0.x; acc[1][1] += p1 * v0.y; acc[1][2] += p1 * v0.z; acc[1][3] += p1 * v0.w;
            acc[1][4] += p1 * v1.x; acc[1][5] += p1 * v1.y; acc[1][6] += p1 * v1.z; acc[1][7] += p1 * v1.w;
            acc[2][0] += p2 * v0.x; acc[2][1] += p2 * v0.y; acc[2][2] += p2 * v0.z; acc[2][3] += p2 * v0.w;
            acc[2][4] += p2 * v1.x; acc[2][5] += p2 * v1.y; acc[2][6] += p2 * v1.z; acc[2][7] += p2 * v1.w;
            acc[3][0] += p3 * v0.x; acc[3][1] += p3 * v0.y; acc[3][2] += p3 * v0.z; acc[3][3] += p3 * v0.w;
            acc[3][4] += p3 * v1.x; acc[3][5] += p3 * v1.y; acc[3][6] += p3 * v1.z; acc[3][7] += p3 * v1.w;
        }
    }

#pragma unroll
    for (int i = 0; i < 4; i++) {
        float inv = 1.0f / lrow[i];
        float* orow = o + ((size_t)(b * QL_ + q0 + ty * 4 + i)) * (NH_ * HD_) + h * HD_;
        ((float4*)orow)[tx] =
            make_float4(acc[i][0] * inv, acc[i][1] * inv, acc[i][2] * inv, acc[i][3] * inv);
        ((float4*)orow)[tx + 16] =
            make_float4(acc[i][4] * inv, acc[i][5] * inv, acc[i][6] * inv, acc[i][7] * inv);
    }
}

// ---------------- launch ----------------
extern "C" void kernel_launch(void* const* d_in, const int* in_sizes, int n_in,
                              void* d_out, int out_size) {
    const float* noise = (const float*)d_in[0];
    const float* ctx   = (const float*)d_in[1];
    const float* cosT  = (const float*)d_in[2];
    const float* sinT  = (const float*)d_in[3];
    const float* Wq    = (const float*)d_in[4];
    const float* Wk    = (const float*)d_in[5];
    const float* Wv    = (const float*)d_in[6];
    const float* Wo    = (const float*)d_in[7];
    const float* qnw   = (const float*)d_in[8];
    const float* knw   = (const float*)d_in[9];
    float* out = (float*)d_out;

    float *qraw, *kraw, *vraw, *qn, *kn, *ao;
    cudaGetSymbolAddress((void**)&qraw, g_qraw);
    cudaGetSymbolAddress((void**)&kraw, g_kraw);
    cudaGetSymbolAddress((void**)&vraw, g_vraw);
    cudaGetSymbolAddress((void**)&qn,   g_qn);
    cudaGetSymbolAddress((void**)&kn,   g_kn);
    cudaGetSymbolAddress((void**)&ao,   g_ao);

    cudaFuncSetAttribute(flash_kernel, cudaFuncAttributeMaxDynamicSharedMemorySize,
                         FLASH_SMEM);

    // projections (tf32 tensor cores, 3xTF32 split)
    gemm_tf32_kernel<false><<<dim3(16, 32), 256>>>(noise, nullptr, nullptr, Wq, qraw,
                                                   B_ * QL_, NH_ * HD_);
    gemm_tf32_kernel<true><<<dim3(4, 128), 256>>>(nullptr, ctx, noise, Wk, kraw,
                                                  B_ * KL_, NKV_ * HD_);
    gemm_tf32_kernel<true><<<dim3(4, 128), 256>>>(nullptr, ctx, noise, Wv, vraw,
                                                  B_ * KL_, NKV_ * HD_);
    // norm + rope
    qnorm_rope_kernel<<<B_ * QL_ * NH_, 128>>>(qraw, cosT, sinT, qnw, qn);
    knorm_rope_kernel<<<B_ * KL_ * NKV_, 128>>>(kraw, cosT, sinT, knw, kn);
    // attention
    flash_kernel<<<dim3(QL_ / 64, NH_, B_), 256, FLASH_SMEM>>>(qn, kn, vraw, ao);
    // output projection
    gemm_tf32_kernel<false><<<dim3(16, 32), 256>>>(ao, nullptr, nullptr, Wo, out,
                                                   B_ * QL_, NH_ * HD_);
}

// round 8
// speedup vs baseline: 1.8725x; 1.1254x over previous
#include <cuda_runtime.h>
#include <cstdint>

// ---------------- problem constants ----------------
#define B_    4
#define QL_   1024
#define CL_   3072
#define KL_   4096      // CL + QL
#define H_    2048
#define NH_   16
#define NKV_  4
#define HD_   128
#define GROUPS_ 4       // NH / NKV

constexpr float EPS_   = 1e-6f;
constexpr float SCALE_ = 0.08838834764831845f; // 128^-0.5

// ---------------- scratch (device globals; no allocations allowed) ----------------
__device__ float g_qraw[(size_t)B_ * QL_ * NH_ * HD_];   // [B*QL, NH*HD]
__device__ float g_kraw[(size_t)B_ * KL_ * NKV_ * HD_];  // [B*KL, NKV*HD]
__device__ float g_vraw[(size_t)B_ * KL_ * NKV_ * HD_];  // [B*KL, NKV*HD]
__device__ float g_qn  [(size_t)B_ * NH_ * QL_ * HD_];   // [B, NH, QL, HD]
__device__ float g_kn  [(size_t)B_ * NKV_ * KL_ * HD_];  // [B, NKV, KL, HD]
__device__ float g_ao  [(size_t)B_ * QL_ * NH_ * HD_];   // [B*QL, NH*HD]

// ---------------- helpers ----------------
template <bool CONCAT>
__device__ __forceinline__ const float* a_rowptr(const float* __restrict__ A,
                                                 const float* __restrict__ ctx,
                                                 const float* __restrict__ noise,
                                                 int r) {
    if (!CONCAT) return A + (size_t)r * H_;
    int b = r >> 12;        // / KL_
    int p = r & (KL_ - 1);  // % KL_
    return (p < CL_) ? ctx + (size_t)(b * CL_ + p) * H_
                     : noise + (size_t)(b * QL_ + (p - CL_)) * H_;
}

__device__ __forceinline__ uint32_t f2tf32(float x) {
    uint32_t r;
    asm("cvt.rna.tf32.f32 %0, %1;" : "=r"(r) : "f"(x));
    return r;
}

__device__ __forceinline__ void splitf(float x, uint32_t& hi, uint32_t& lo) {
    hi = f2tf32(x);
    lo = f2tf32(x - __uint_as_float(hi));
}

__device__ __forceinline__ void mma_tf32(float* c, const uint32_t* a, const uint32_t* b) {
    asm volatile(
        "mma.sync.aligned.m16n8k8.row.col.f32.tf32.tf32.f32 "
        "{%0,%1,%2,%3}, {%4,%5,%6,%7}, {%8,%9}, {%0,%1,%2,%3};\n"
        : "+f"(c[0]), "+f"(c[1]), "+f"(c[2]), "+f"(c[3])
        : "r"(a[0]), "r"(a[1]), "r"(a[2]), "r"(a[3]), "r"(b[0]), "r"(b[1]));
}

// ---------------- tf32 tensor-core GEMM (3xTF32 split => ~fp32 accuracy) ----------------
#define APAD 36
#define BPAD 132

template <bool CONCAT>
__global__ __launch_bounds__(256) void gemm_tf32_kernel(
    const float* __restrict__ A, const float* __restrict__ ctx,
    const float* __restrict__ noise, const float* __restrict__ W,
    float* __restrict__ C, int M, int N) {
    __shared__ float As[128 * APAD];
    __shared__ float Bs[32 * BPAD];

    const int tid  = threadIdx.x;
    const int lane = tid & 31;
    const int wid  = tid >> 5;
    const int warp_m = wid & 3;
    const int warp_n = wid >> 2;

    const int row0 = blockIdx.y * 128;
    const int col0 = blockIdx.x * 128;

    const int ka = (tid & 7) * 4;
    const int ar = tid >> 3;
    const int nb = (tid & 31) * 4;
    const int kb = tid >> 5;

    const float* arow[4];
#pragma unroll
    for (int i = 0; i < 4; i++)
        arow[i] = a_rowptr<CONCAT>(A, ctx, noise, row0 + ar + 32 * i);

    const int l4 = lane >> 2;
    const int lk = lane & 3;

    float acc[2][8][4];
#pragma unroll
    for (int mt = 0; mt < 2; mt++)
#pragma unroll
        for (int nt = 0; nt < 8; nt++)
#pragma unroll
            for (int c = 0; c < 4; c++) acc[mt][nt][c] = 0.0f;

    for (int k0 = 0; k0 < H_; k0 += 32) {
        float4 areg[4], breg[4];
#pragma unroll
        for (int i = 0; i < 4; i++)
            areg[i] = *(const float4*)(arow[i] + k0 + ka);
#pragma unroll
        for (int i = 0; i < 4; i++)
            breg[i] = *(const float4*)(W + (size_t)(k0 + kb + 8 * i) * N + col0 + nb);

        __syncthreads();
#pragma unroll
        for (int i = 0; i < 4; i++)
            *(float4*)&As[(ar + 32 * i) * APAD + ka] = areg[i];
#pragma unroll
        for (int i = 0; i < 4; i++)
            *(float4*)&Bs[(kb + 8 * i) * BPAD + nb] = breg[i];
        __syncthreads();

#pragma unroll
        for (int kk = 0; kk < 32; kk += 8) {
            uint32_t ahi[2][4], alo[2][4];
#pragma unroll
            for (int mt = 0; mt < 2; mt++) {
                int r0 = (warp_m * 32 + mt * 16 + l4) * APAD;
                int r1 = r0 + 8 * APAD;
                splitf(As[r0 + kk + lk],     ahi[mt][0], alo[mt][0]);
                splitf(As[r1 + kk + lk],     ahi[mt][1], alo[mt][1]);
                splitf(As[r0 + kk + lk + 4], ahi[mt][2], alo[mt][2]);
                splitf(As[r1 + kk + lk + 4], ahi[mt][3], alo[mt][3]);
            }
            uint32_t bhi[8][2], blo[8][2];
#pragma unroll
            for (int nt = 0; nt < 8; nt++) {
                int cn = warp_n * 64 + nt * 8 + l4;
                splitf(Bs[(kk + lk) * BPAD + cn],     bhi[nt][0], blo[nt][0]);
                splitf(Bs[(kk + lk + 4) * BPAD + cn], bhi[nt][1], blo[nt][1]);
            }
#pragma unroll
            for (int mt = 0; mt < 2; mt++)
#pragma unroll
                for (int nt = 0; nt < 8; nt++) {
                    mma_tf32(acc[mt][nt], ahi[mt], bhi[nt]);
                    mma_tf32(acc[mt][nt], ahi[mt], blo[nt]);
                    mma_tf32(acc[mt][nt], alo[mt], bhi[nt]);
                }
        }
    }

#pragma unroll
    for (int mt = 0; mt < 2; mt++) {
        int r0 = row0 + warp_m * 32 + mt * 16 + l4;
#pragma unroll
        for (int nt = 0; nt < 8; nt++) {
            int cn = col0 + warp_n * 64 + nt * 8 + 2 * lk;
            *(float2*)(C + (size_t)r0 * N + cn) = make_float2(acc[mt][nt][0], acc[mt][nt][1]);
            *(float2*)(C + (size_t)(r0 + 8) * N + cn) = make_float2(acc[mt][nt][2], acc[mt][nt][3]);
        }
    }
}

// ---------------- RMSNorm + RoPE ----------------
__device__ __forceinline__ float block_sum128(float v, float* red) {
#pragma unroll
    for (int o = 16; o; o >>= 1) v += __shfl_xor_sync(0xffffffffu, v, o);
    if ((threadIdx.x & 31) == 0) red[threadIdx.x >> 5] = v;
    __syncthreads();
    return red[0] + red[1] + red[2] + red[3];
}

__global__ __launch_bounds__(128) void qnorm_rope_kernel(
    const float* __restrict__ qraw, const float* __restrict__ cosT,
    const float* __restrict__ sinT, const float* __restrict__ w,
    float* __restrict__ qout) {
    __shared__ float red[4];
    __shared__ float sx[128];
    const int blk = blockIdx.x;
    const int h   = blk & (NH_ - 1);
    const int row = blk >> 4;
    const int b   = row >> 10;
    const int qi  = row & (QL_ - 1);
    const int t   = threadIdx.x;

    float x = qraw[(size_t)row * (NH_ * HD_) + h * HD_ + t];
    float ss = block_sum128(x * x, red);
    float inv = rsqrtf(ss * (1.0f / HD_) + EPS_);
    float xn = x * inv * w[t];
    sx[t] = xn;
    __syncthreads();
    float rot = (t < 64) ? -sx[t + 64] : sx[t - 64];
    int pos = CL_ + qi;
    size_t ci = ((size_t)b * KL_ + pos) * HD_ + t;
    float outv = xn * cosT[ci] + rot * sinT[ci];
    qout[(((size_t)(b * NH_ + h) * QL_) + qi) * HD_ + t] = outv;
}

__global__ __launch_bounds__(128) void knorm_rope_kernel(
    const float* __restrict__ kraw, const float* __restrict__ cosT,
    const float* __restrict__ sinT, const float* __restrict__ w,
    float* __restrict__ kout) {
    __shared__ float red[4];
    __shared__ float sx[128];
    const int blk = blockIdx.x;
    const int kvh = blk & (NKV_ - 1);
    const int row = blk >> 2;
    const int b   = row >> 12;
    const int p   = row & (KL_ - 1);
    const int t   = threadIdx.x;

    float x = kraw[(size_t)row * (NKV_ * HD_) + kvh * HD_ + t];
    float ss = block_sum128(x * x, red);
    float inv = rsqrtf(ss * (1.0f / HD_) + EPS_);
    float xn = x * inv * w[t];
    sx[t] = xn;
    __syncthreads();
    float rot = (t < 64) ? -sx[t + 64] : sx[t - 64];
    size_t ci = ((size_t)b * KL_ + p) * HD_ + t;
    float outv = xn * cosT[ci] + rot * sinT[ci];
    kout[(((size_t)(b * NKV_ + kvh) * KL_) + p) * HD_ + t] = outv;
}

// ---------------- tensor-core flash attention (tf32 3x split) ----------------
// Block: 256 thr = 8 warps. Tile: 128 q x 64 k. Warp w owns q rows [w*16, w*16+16).
// Softmax fully warp-local (rows live in lane%4 groups).
// smem strides chosen for conflict-free fragment LDS:
//   Qs 132 (a=4: A-frag 4*l4+lk unique), Ks 132 (B-frag keys: 4*l4+lk unique),
//   Vs 136 (a=8: B-frag d: 8*lk+l4 unique), Ps 68 (a=4: A-frag 4*l4+lk unique).
constexpr int QSTR = 132, KSTR = 132, VSTR = 136, PSTR = 68;
constexpr int FLASH_SMEM = (128 * QSTR + 64 * KSTR + 64 * VSTR + 128 * PSTR) * 4; // 171008

__global__ __launch_bounds__(256, 1) void flash_mma_kernel(
    const float* __restrict__ q, const float* __restrict__ k,
    const float* __restrict__ vraw, float* __restrict__ o) {
    extern __shared__ float sm[];
    float* Qs = sm;                     // [128][132]
    float* Ks = Qs + 128 * QSTR;        // [64][132]
    float* Vs = Ks + 64 * KSTR;         // [64][136]
    float* Ps = Vs + 64 * VSTR;         // [128][68]

    const int b   = blockIdx.z;
    const int h   = blockIdx.y;
    const int q0  = blockIdx.x * 128;
    const int kvh = h >> 2;
    const int tid = threadIdx.x;
    const int lane = tid & 31;
    const int w    = tid >> 5;
    const int l4   = lane >> 2;
    const int lk   = lane & 3;

    // load Q tile [128,128], pre-scaled by SCALE_
    const float4* qsrc = (const float4*)(q + (((size_t)(b * NH_ + h) * QL_ + q0) * HD_));
    for (int i = tid; i < 128 * 32; i += 256) {
        int r = i >> 5, c = i & 31;
        float4 v = qsrc[i];
        *(float4*)&Qs[r * QSTR + 4 * c] =
            make_float4(v.x * SCALE_, v.y * SCALE_, v.z * SCALE_, v.w * SCALE_);
    }

    float mA = -3.0e38f, mB = -3.0e38f, lA = 0.0f, lB = 0.0f;
    float O[16][4];
#pragma unroll
    for (int nt = 0; nt < 16; nt++)
#pragma unroll
        for (int c = 0; c < 4; c++) O[nt][c] = 0.0f;

    const float* kbase = k + (size_t)(b * NKV_ + kvh) * KL_ * HD_;
    const float4* vbase4 = (const float4*)vraw;

    const float* qrowA = &Qs[(w * 16 + l4) * QSTR];
    const float* qrowB = qrowA + 8 * QSTR;
    float* prowA = &Ps[(w * 16 + l4) * PSTR];
    float* prowB = prowA + 8 * PSTR;

    for (int k0 = 0; k0 < KL_; k0 += 64) {
        __syncthreads();
        for (int i = tid; i < 64 * 32; i += 256) {
            int r = i >> 5, c = i & 31;
            *(float4*)&Ks[r * KSTR + 4 * c] =
                *(const float4*)(kbase + (size_t)(k0 + r) * HD_ + 4 * c);
            *(float4*)&Vs[r * VSTR + 4 * c] =
                vbase4[(size_t)(b * KL_ + k0 + r) * 128 + kvh * 32 + c];
        }
        __syncthreads();

        // ---- S = Q @ K^T (16 x 64 per warp) ----
        float Sf[8][4];
#pragma unroll
        for (int nt = 0; nt < 8; nt++)
#pragma unroll
            for (int c = 0; c < 4; c++) Sf[nt][c] = 0.0f;

#pragma unroll
        for (int kk = 0; kk < 16; kk++) {
            const int c0 = kk * 8 + lk;
            uint32_t ahi[4], alo[4];
            splitf(qrowA[c0],     ahi[0], alo[0]);
            splitf(qrowB[c0],     ahi[1], alo[1]);
            splitf(qrowA[c0 + 4], ahi[2], alo[2]);
            splitf(qrowB[c0 + 4], ahi[3], alo[3]);
#pragma unroll
            for (int nt = 0; nt < 8; nt++) {
                uint32_t bhi[2], blo[2];
                splitf(Ks[(nt * 8 + l4) * KSTR + c0],     bhi[0], blo[0]);
                splitf(Ks[(nt * 8 + l4) * KSTR + c0 + 4], bhi[1], blo[1]);
                mma_tf32(Sf[nt], ahi, bhi);
                mma_tf32(Sf[nt], ahi, blo);
                mma_tf32(Sf[nt], alo, bhi);
            }
        }

        // ---- online softmax (warp-local; rows rA=l4, rB=l4+8 of warp tile) ----
        float mxA = Sf[0][0], mxB = Sf[0][2];
#pragma unroll
        for (int nt = 0; nt < 8; nt++) {
            mxA = fmaxf(mxA, fmaxf(Sf[nt][0], Sf[nt][1]));
            mxB = fmaxf(mxB, fmaxf(Sf[nt][2], Sf[nt][3]));
        }
        mxA = fmaxf(mxA, __shfl_xor_sync(0xffffffffu, mxA, 1));
        mxA = fmaxf(mxA, __shfl_xor_sync(0xffffffffu, mxA, 2));
        mxB = fmaxf(mxB, __shfl_xor_sync(0xffffffffu, mxB, 1));
        mxB = fmaxf(mxB, __shfl_xor_sync(0xffffffffu, mxB, 2));

        float mnA = fmaxf(mA, mxA), mnB = fmaxf(mB, mxB);
        float cA = __expf(mA - mnA), cB = __expf(mB - mnB);
        mA = mnA; mB = mnB;

        float sA = 0.0f, sB = 0.0f;
#pragma unroll
        for (int nt = 0; nt < 8; nt++) {
            float p0 = __expf(Sf[nt][0] - mnA), p1 = __expf(Sf[nt][1] - mnA);
            float p2 = __expf(Sf[nt][2] - mnB), p3 = __expf(Sf[nt][3] - mnB);
            sA += p0 + p1; sB += p2 + p3;
            *(float2*)&prowA[nt * 8 + 2 * lk] = make_float2(p0, p1);
            *(float2*)&prowB[nt * 8 + 2 * lk] = make_float2(p2, p3);
        }
        sA += __shfl_xor_sync(0xffffffffu, sA, 1);
        sA += __shfl_xor_sync(0xffffffffu, sA, 2);
        sB += __shfl_xor_sync(0xffffffffu, sB, 1);
        sB += __shfl_xor_sync(0xffffffffu, sB, 2);
        lA = lA * cA + sA;
        lB = lB * cB + sB;

#pragma unroll
        for (int nt = 0; nt < 16; nt++) {
            O[nt][0] *= cA; O[nt][1] *= cA;
            O[nt][2] *= cB; O[nt][3] *= cB;
        }
        __syncwarp();

        // ---- O += P @ V (16 x 128 per warp) ----
#pragma unroll
        for (int kt = 0; kt < 8; kt++) {
            const int ck = kt * 8 + lk;
            uint32_t phi[4], plo[4];
            splitf(prowA[ck],     phi[0], plo[0]);
            splitf(prowB[ck],     phi[1], plo[1]);
            splitf(prowA[ck + 4], phi[2], plo[2]);
            splitf(prowB[ck + 4], phi[3], plo[3]);
#pragma unroll
            for (int nt = 0; nt < 16; nt++) {
                uint32_t vhi[2], vlo[2];
                splitf(Vs[(kt * 8 + lk) * VSTR + nt * 8 + l4],     vhi[0], vlo[0]);
                splitf(Vs[(kt * 8 + lk + 4) * VSTR + nt * 8 + l4], vhi[1], vlo[1]);
                mma_tf32(O[nt], phi, vhi);
                mma_tf32(O[nt], phi, vlo);
                mma_tf32(O[nt], plo, vhi);
            }
        }
    }

    // ---- epilogue: O /= l, write [B*QL, NH*HD] ----
    float iA = 1.0f / lA, iB = 1.0f / lB;
    const int rowA = q0 + w * 16 + l4;
    float* obase = o + ((size_t)(b * QL_ + rowA)) * (NH_ * HD_) + h * HD_;
#pragma unroll
    for (int nt = 0; nt < 16; nt++) {
        *(float2*)(obase + nt * 8 + 2 * lk) =
            make_float2(O[nt][0] * iA, O[nt][1] * iA);
        *(float2*)(obase + (size_t)8 * (NH_ * HD_) + nt * 8 + 2 * lk) =
            make_float2(O[nt][2] * iB, O[nt][3] * iB);
    }
}

// ---------------- launch ----------------
extern "C" void kernel_launch(void* const* d_in, const int* in_sizes, int n_in,
                              void* d_out, int out_size) {
    const float* noise = (const float*)d_in[0];
    const float* ctx   = (const float*)d_in[1];
    const float* cosT  = (const float*)d_in[2];
    const float* sinT  = (const float*)d_in[3];
    const float* Wq    = (const float*)d_in[4];
    const float* Wk    = (const float*)d_in[5];
    const float* Wv    = (const float*)d_in[6];
    const float* Wo    = (const float*)d_in[7];
    const float* qnw   = (const float*)d_in[8];
    const float* knw   = (const float*)d_in[9];
    float* out = (float*)d_out;

    float *qraw, *kraw, *vraw, *qn, *kn, *ao;
    cudaGetSymbolAddress((void**)&qraw, g_qraw);
    cudaGetSymbolAddress((void**)&kraw, g_kraw);
    cudaGetSymbolAddress((void**)&vraw, g_vraw);
    cudaGetSymbolAddress((void**)&qn,   g_qn);
    cudaGetSymbolAddress((void**)&kn,   g_kn);
    cudaGetSymbolAddress((void**)&ao,   g_ao);

    cudaFuncSetAttribute(flash_mma_kernel, cudaFuncAttributeMaxDynamicSharedMemorySize,
                         FLASH_SMEM);

    // projections (tf32 tensor cores, 3xTF32 split)
    gemm_tf32_kernel<false><<<dim3(16, 32), 256>>>(noise, nullptr, nullptr, Wq, qraw,
                                                   B_ * QL_, NH_ * HD_);
    gemm_tf32_kernel<true><<<dim3(4, 128), 256>>>(nullptr, ctx, noise, Wk, kraw,
                                                  B_ * KL_, NKV_ * HD_);
    gemm_tf32_kernel<true><<<dim3(4, 128), 256>>>(nullptr, ctx, noise, Wv, vraw,
                                                  B_ * KL_, NKV_ * HD_);
    // norm + rope
    qnorm_rope_kernel<<<B_ * QL_ * NH_, 128>>>(qraw, cosT, sinT, qnw, qn);
    knorm_rope_kernel<<<B_ * KL_ * NKV_, 128>>>(kraw, cosT, sinT, knw, kn);
    // attention (tensor cores)
    flash_mma_kernel<<<dim3(QL_ / 128, NH_, B_), 256, FLASH_SMEM>>>(qn, kn, vraw, ao);
    // output projection
    gemm_tf32_kernel<false><<<dim3(16, 32), 256>>>(ao, nullptr, nullptr, Wo, out,
                                                   B_ * QL_, NH_ * HD_);
}

// round 12
// speedup vs baseline: 2.3317x; 1.2453x over previous
#include <cuda_runtime.h>
#include <cuda_bf16.h>
#include <cstdint>

// ---------------- problem constants ----------------
#define B_    4
#define QL_   1024
#define CL_   3072
#define KL_   4096      // CL + QL
#define H_    2048
#define NH_   16
#define NKV_  4
#define HD_   128
#define GROUPS_ 4       // NH / NKV

constexpr float EPS_   = 1e-6f;
constexpr float SCALE_ = 0.08838834764831845f; // 128^-0.5

// ---------------- scratch (device globals; no allocations allowed) ----------------
__device__ float g_qraw[(size_t)B_ * QL_ * NH_ * HD_];   // [B*QL, NH*HD]
__device__ float g_kraw[(size_t)B_ * KL_ * NKV_ * HD_];  // [B*KL, NKV*HD]
__device__ float g_vraw[(size_t)B_ * KL_ * NKV_ * HD_];  // [B*KL, NKV*HD]
__device__ float g_qn  [(size_t)B_ * NH_ * QL_ * HD_];   // [B, NH, QL, HD]
__device__ float g_kn  [(size_t)B_ * NKV_ * KL_ * HD_];  // [B, NKV, KL, HD]
__device__ float g_ao  [(size_t)B_ * QL_ * NH_ * HD_];   // [B*QL, NH*HD]

// ---------------- helpers ----------------
template <bool CONCAT>
__device__ __forceinline__ const float* a_rowptr(const float* __restrict__ A,
                                                 const float* __restrict__ ctx,
                                                 const float* __restrict__ noise,
                                                 int r) {
    if (!CONCAT) return A + (size_t)r * H_;
    int b = r >> 12;        // / KL_
    int p = r & (KL_ - 1);  // % KL_
    return (p < CL_) ? ctx + (size_t)(b * CL_ + p) * H_
                     : noise + (size_t)(b * QL_ + (p - CL_)) * H_;
}

__device__ __forceinline__ uint32_t f2tf32(float x) {
    uint32_t r;
    asm("cvt.rna.tf32.f32 %0, %1;" : "=r"(r) : "f"(x));
    return r;
}

__device__ __forceinline__ void splitf(float x, uint32_t& hi, uint32_t& lo) {
    hi = f2tf32(x);
    lo = f2tf32(x - __uint_as_float(hi));
}

__device__ __forceinline__ void mma_tf32(float* c, const uint32_t* a, const uint32_t* b) {
    asm volatile(
        "mma.sync.aligned.m16n8k8.row.col.f32.tf32.tf32.f32 "
        "{%0,%1,%2,%3}, {%4,%5,%6,%7}, {%8,%9}, {%0,%1,%2,%3};\n"
        : "+f"(c[0]), "+f"(c[1]), "+f"(c[2]), "+f"(c[3])
        : "r"(a[0]), "r"(a[1]), "r"(a[2]), "r"(a[3]), "r"(b[0]), "r"(b[1]));
}

// bf16 pair pack: result lower16 = bf16(x0), upper16 = bf16(x1)
__device__ __forceinline__ uint32_t packbf2(float x0, float x1) {
    uint32_t r;
    asm("cvt.rn.bf16x2.f32 %0, %1, %2;" : "=r"(r) : "f"(x1), "f"(x0));
    return r;
}
// split pair into hi/lo bf16x2 words
__device__ __forceinline__ void splitbf2(float x0, float x1, uint32_t& hi, uint32_t& lo) {
    hi = packbf2(x0, x1);
    float h0 = __uint_as_float(hi << 16);
    float h1 = __uint_as_float(hi & 0xffff0000u);
    lo = packbf2(x0 - h0, x1 - h1);
}

__device__ __forceinline__ void mma_bf16(float* c, const uint32_t* a, const uint32_t* b) {
    asm volatile(
        "mma.sync.aligned.m16n8k16.row.col.f32.bf16.bf16.f32 "
        "{%0,%1,%2,%3}, {%4,%5,%6,%7}, {%8,%9}, {%0,%1,%2,%3};\n"
        : "+f"(c[0]), "+f"(c[1]), "+f"(c[2]), "+f"(c[3])
        : "r"(a[0]), "r"(a[1]), "r"(a[2]), "r"(a[3]), "r"(b[0]), "r"(b[1]));
}

// ---------------- tf32 tensor-core GEMM (3xTF32 split => ~fp32 accuracy) ----------------
#define APAD 36
#define BPAD 132

template <bool CONCAT>
__global__ __launch_bounds__(256) void gemm_tf32_kernel(
    const float* __restrict__ A, const float* __restrict__ ctx,
    const float* __restrict__ noise, const float* __restrict__ W,
    float* __restrict__ C, int M, int N) {
    __shared__ float As[128 * APAD];
    __shared__ float Bs[32 * BPAD];

    const int tid  = threadIdx.x;
    const int lane = tid & 31;
    const int wid  = tid >> 5;
    const int warp_m = wid & 3;
    const int warp_n = wid >> 2;

    const int row0 = blockIdx.y * 128;
    const int col0 = blockIdx.x * 128;

    const int ka = (tid & 7) * 4;
    const int ar = tid >> 3;
    const int nb = (tid & 31) * 4;
    const int kb = tid >> 5;

    const float* arow[4];
#pragma unroll
    for (int i = 0; i < 4; i++)
        arow[i] = a_rowptr<CONCAT>(A, ctx, noise, row0 + ar + 32 * i);

    const int l4 = lane >> 2;
    const int lk = lane & 3;

    float acc[2][8][4];
#pragma unroll
    for (int mt = 0; mt < 2; mt++)
#pragma unroll
        for (int nt = 0; nt < 8; nt++)
#pragma unroll
            for (int c = 0; c < 4; c++) acc[mt][nt][c] = 0.0f;

    for (int k0 = 0; k0 < H_; k0 += 32) {
        float4 areg[4], breg[4];
#pragma unroll
        for (int i = 0; i < 4; i++)
            areg[i] = *(const float4*)(arow[i] + k0 + ka);
#pragma unroll
        for (int i = 0; i < 4; i++)
            breg[i] = *(const float4*)(W + (size_t)(k0 + kb + 8 * i) * N + col0 + nb);

        __syncthreads();
#pragma unroll
        for (int i = 0; i < 4; i++)
            *(float4*)&As[(ar + 32 * i) * APAD + ka] = areg[i];
#pragma unroll
        for (int i = 0; i < 4; i++)
            *(float4*)&Bs[(kb + 8 * i) * BPAD + nb] = breg[i];
        __syncthreads();

#pragma unroll
        for (int kk = 0; kk < 32; kk += 8) {
            uint32_t ahi[2][4], alo[2][4];
#pragma unroll
            for (int mt = 0; mt < 2; mt++) {
                int r0 = (warp_m * 32 + mt * 16 + l4) * APAD;
                int r1 = r0 + 8 * APAD;
                splitf(As[r0 + kk + lk],     ahi[mt][0], alo[mt][0]);
                splitf(As[r1 + kk + lk],     ahi[mt][1], alo[mt][1]);
                splitf(As[r0 + kk + lk + 4], ahi[mt][2], alo[mt][2]);
                splitf(As[r1 + kk + lk + 4], ahi[mt][3], alo[mt][3]);
            }
            uint32_t bhi[8][2], blo[8][2];
#pragma unroll
            for (int nt = 0; nt < 8; nt++) {
                int cn = warp_n * 64 + nt * 8 + l4;
                splitf(Bs[(kk + lk) * BPAD + cn],     bhi[nt][0], blo[nt][0]);
                splitf(Bs[(kk + lk + 4) * BPAD + cn], bhi[nt][1], blo[nt][1]);
            }
#pragma unroll
            for (int mt = 0; mt < 2; mt++)
#pragma unroll
                for (int nt = 0; nt < 8; nt++) {
                    mma_tf32(acc[mt][nt], ahi[mt], bhi[nt]);
                    mma_tf32(acc[mt][nt], ahi[mt], blo[nt]);
                    mma_tf32(acc[mt][nt], alo[mt], bhi[nt]);
                }
        }
    }

#pragma unroll
    for (int mt = 0; mt < 2; mt++) {
        int r0 = row0 + warp_m * 32 + mt * 16 + l4;
#pragma unroll
        for (int nt = 0; nt < 8; nt++) {
            int cn = col0 + warp_n * 64 + nt * 8 + 2 * lk;
            *(float2*)(C + (size_t)r0 * N + cn) = make_float2(acc[mt][nt][0], acc[mt][nt][1]);
            *(float2*)(C + (size_t)(r0 + 8) * N + cn) = make_float2(acc[mt][nt][2], acc[mt][nt][3]);
        }
    }
}

// ---------------- RMSNorm + RoPE ----------------
__device__ __forceinline__ float block_sum128(float v, float* red) {
#pragma unroll
    for (int o = 16; o; o >>= 1) v += __shfl_xor_sync(0xffffffffu, v, o);
    if ((threadIdx.x & 31) == 0) red[threadIdx.x >> 5] = v;
    __syncthreads();
    return red[0] + red[1] + red[2] + red[3];
}

__global__ __launch_bounds__(128) void qnorm_rope_kernel(
    const float* __restrict__ qraw, const float* __restrict__ cosT,
    const float* __restrict__ sinT, const float* __restrict__ w,
    float* __restrict__ qout) {
    __shared__ float red[4];
    __shared__ float sx[128];
    const int blk = blockIdx.x;
    const int h   = blk & (NH_ - 1);
    const int row = blk >> 4;
    const int b   = row >> 10;
    const int qi  = row & (QL_ - 1);
    const int t   = threadIdx.x;

    float x = qraw[(size_t)row * (NH_ * HD_) + h * HD_ + t];
    float ss = block_sum128(x * x, red);
    float inv = rsqrtf(ss * (1.0f / HD_) + EPS_);
    float xn = x * inv * w[t];
    sx[t] = xn;
    __syncthreads();
    float rot = (t < 64) ? -sx[t + 64] : sx[t - 64];
    int pos = CL_ + qi;
    size_t ci = ((size_t)b * KL_ + pos) * HD_ + t;
    float outv = xn * cosT[ci] + rot * sinT[ci];
    qout[(((size_t)(b * NH_ + h) * QL_) + qi) * HD_ + t] = outv;
}

__global__ __launch_bounds__(128) void knorm_rope_kernel(
    const float* __restrict__ kraw, const float* __restrict__ cosT,
    const float* __restrict__ sinT, const float* __restrict__ w,
    float* __restrict__ kout) {
    __shared__ float red[4];
    __shared__ float sx[128];
    const int blk = blockIdx.x;
    const int kvh = blk & (NKV_ - 1);
    const int row = blk >> 2;
    const int b   = row >> 12;
    const int p   = row & (KL_ - 1);
    const int t   = threadIdx.x;

    float x = kraw[(size_t)row * (NKV_ * HD_) + kvh * HD_ + t];
    float ss = block_sum128(x * x, red);
    float inv = rsqrtf(ss * (1.0f / HD_) + EPS_);
    float xn = x * inv * w[t];
    sx[t] = xn;
    __syncthreads();
    float rot = (t < 64) ? -sx[t + 64] : sx[t - 64];
    size_t ci = ((size_t)b * KL_ + p) * HD_ + t;
    float outv = xn * cosT[ci] + rot * sinT[ci];
    kout[(((size_t)(b * NKV_ + kvh) * KL_) + p) * HD_ + t] = outv;
}

// ---------------- bf16x3 tensor-core flash attention ----------------
// Block: 256 thr = 8 warps. Tile: 128 q x 64 k. Warp w owns q rows [w*16, w*16+16).
// All operands pre-split into bf16 hi/lo planes in smem (packed bf16x2 words,
// k-pairs contiguous). V stored transposed [dim][key]. Strides (in 32-bit words)
// all ≡ 4 (mod 32) => conflict-free fragment LDS.
constexpr int QW = 68;   // Q plane row stride (words): 64 + 4
constexpr int KW = 68;   // K plane row stride
constexpr int VW = 36;   // V^T plane row stride: 32 + 4
constexpr int PW = 36;   // P plane row stride
constexpr int FLASH_SMEM =
    (2 * 128 * QW + 2 * 64 * KW + 2 * 128 * VW + 2 * 128 * PW) * 4; // 178176 B

__global__ __launch_bounds__(256, 1) void flash_bf16_kernel(
    const float* __restrict__ q, const float* __restrict__ k,
    const float* __restrict__ vraw, float* __restrict__ o) {
    extern __shared__ uint32_t smu[];
    uint32_t* Qhi = smu;
    uint32_t* Qlo = Qhi + 128 * QW;
    uint32_t* Khi = Qlo + 128 * QW;
    uint32_t* Klo = Khi + 64 * KW;
    uint32_t* Vhi = Klo + 64 * KW;     // V^T: [128 dims][VW]
    uint32_t* Vlo = Vhi + 128 * VW;
    uint32_t* Phi = Vlo + 128 * VW;    // [128 q][PW]
    uint32_t* Plo = Phi + 128 * PW;

    const int b   = blockIdx.z;
    const int h   = blockIdx.y;
    const int q0  = blockIdx.x * 128;
    const int kvh = h >> 2;
    const int tid = threadIdx.x;
    const int lane = tid & 31;
    const int w    = tid >> 5;
    const int l4   = lane >> 2;
    const int lk   = lane & 3;

    // ---- load Q tile [128,128]: scale, split into bf16 hi/lo planes ----
    const float4* qsrc = (const float4*)(q + (((size_t)(b * NH_ + h) * QL_ + q0) * HD_));
    for (int i = tid; i < 128 * 32; i += 256) {
        int r = i >> 5, c = i & 31;
        float4 v = qsrc[i];
        uint32_t h0, l0, h1, l1;
        splitbf2(v.x * SCALE_, v.y * SCALE_, h0, l0);
        splitbf2(v.z * SCALE_, v.w * SCALE_, h1, l1);
        *(uint2*)&Qhi[r * QW + 2 * c] = make_uint2(h0, h1);
        *(uint2*)&Qlo[r * QW + 2 * c] = make_uint2(l0, l1);
    }

    float mA = -3.0e38f, mB = -3.0e38f, lA = 0.0f, lB = 0.0f;
    float O[16][4];
#pragma unroll
    for (int nt = 0; nt < 16; nt++)
#pragma unroll
        for (int c = 0; c < 4; c++) O[nt][c] = 0.0f;

    const float* kbase = k + (size_t)(b * NKV_ + kvh) * KL_ * HD_;
    const float4* vbase4 = (const float4*)vraw;

    const int rowA = w * 16 + l4;
    const int rowB = rowA + 8;

    for (int k0 = 0; k0 < KL_; k0 += 64) {
        __syncthreads();
        // ---- K tile [64 keys][128 dims] -> hi/lo planes ----
        for (int i = tid; i < 64 * 32; i += 256) {
            int r = i >> 5, c = i & 31;
            float4 kv = *(const float4*)(kbase + (size_t)(k0 + r) * HD_ + 4 * c);
            uint32_t h0, l0, h1, l1;
            splitbf2(kv.x, kv.y, h0, l0);
            splitbf2(kv.z, kv.w, h1, l1);
            *(uint2*)&Khi[r * KW + 2 * c] = make_uint2(h0, h1);
            *(uint2*)&Klo[r * KW + 2 * c] = make_uint2(l0, l1);
        }
        // ---- V tile transposed: V^T[dim][key] hi/lo planes ----
        for (int i = tid; i < 64 * 32; i += 256) {
            int key = i & 63, dg = i >> 6;   // dg: dim group of 4
            float4 vv = vbase4[(size_t)(b * KL_ + k0 + key) * 128 + kvh * 32 + dg];
            float vals[4] = {vv.x, vv.y, vv.z, vv.w};
#pragma unroll
            for (int j = 0; j < 4; j++) {
                __nv_bfloat16 hb = __float2bfloat16(vals[j]);
                __nv_bfloat16 lb = __float2bfloat16(vals[j] - __bfloat162float(hb));
                ((__nv_bfloat16*)Vhi)[(size_t)(4 * dg + j) * (2 * VW) + key] = hb;
                ((__nv_bfloat16*)Vlo)[(size_t)(4 * dg + j) * (2 * VW) + key] = lb;
            }
        }
        __syncthreads();

        // ---- S = Q @ K^T (16 x 64 per warp), 3xBF16 ----
        float Sf[8][4];
#pragma unroll
        for (int nt = 0; nt < 8; nt++)
#pragma unroll
            for (int c = 0; c < 4; c++) Sf[nt][c] = 0.0f;

#pragma unroll
        for (int kk = 0; kk < 8; kk++) {     // k=16 per step over HD=128
            const int c0 = kk * 8 + lk;
            uint32_t aH[4], aL[4];
            aH[0] = Qhi[rowA * QW + c0];     aL[0] = Qlo[rowA * QW + c0];
            aH[1] = Qhi[rowB * QW + c0];     aL[1] = Qlo[rowB * QW + c0];
            aH[2] = Qhi[rowA * QW + c0 + 4]; aL[2] = Qlo[rowA * QW + c0 + 4];
            aH[3] = Qhi[rowB * QW + c0 + 4]; aL[3] = Qlo[rowB * QW + c0 + 4];
#pragma unroll
            for (int nt = 0; nt < 8; nt++) {
                const int kr = (nt * 8 + l4) * KW + c0;
                uint32_t bH[2], bL[2];
                bH[0] = Khi[kr];     bH[1] = Khi[kr + 4];
                bL[0] = Klo[kr];     bL[1] = Klo[kr + 4];
                mma_bf16(Sf[nt], aH, bH);
                mma_bf16(Sf[nt], aL, bH);
                mma_bf16(Sf[nt], aH, bL);
            }
        }

        // ---- online softmax (warp-local) ----
        float mxA = Sf[0][0], mxB = Sf[0][2];
#pragma unroll
        for (int nt = 0; nt < 8; nt++) {
            mxA = fmaxf(mxA, fmaxf(Sf[nt][0], Sf[nt][1]));
            mxB = fmaxf(mxB, fmaxf(Sf[nt][2], Sf[nt][3]));
        }
        mxA = fmaxf(mxA, __shfl_xor_sync(0xffffffffu, mxA, 1));
        mxA = fmaxf(mxA, __shfl_xor_sync(0xffffffffu, mxA, 2));
        mxB = fmaxf(mxB, __shfl_xor_sync(0xffffffffu, mxB, 1));
        mxB = fmaxf(mxB, __shfl_xor_sync(0xffffffffu, mxB, 2));

        float mnA = fmaxf(mA, mxA), mnB = fmaxf(mB, mxB);
        float cA = __expf(mA - mnA), cB = __expf(mB - mnB);
        mA = mnA; mB = mnB;

        float sA = 0.0f, sB = 0.0f;
#pragma unroll
        for (int nt = 0; nt < 8; nt++) {
            float p0 = __expf(Sf[nt][0] - mnA), p1 = __expf(Sf[nt][1] - mnA);
            float p2 = __expf(Sf[nt][2] - mnB), p3 = __expf(Sf[nt][3] - mnB);
            sA += p0 + p1; sB += p2 + p3;
            uint32_t hA, lA2, hB, lB2;
            splitbf2(p0, p1, hA, lA2);
            splitbf2(p2, p3, hB, lB2);
            Phi[rowA * PW + nt * 4 + lk] = hA;
            Plo[rowA * PW + nt * 4 + lk] = lA2;
            Phi[rowB * PW + nt * 4 + lk] = hB;
            Plo[rowB * PW + nt * 4 + lk] = lB2;
        }
        sA += __shfl_xor_sync(0xffffffffu, sA, 1);
        sA += __shfl_xor_sync(0xffffffffu, sA, 2);
        sB += __shfl_xor_sync(0xffffffffu, sB, 1);
        sB += __shfl_xor_sync(0xffffffffu, sB, 2);
        lA = lA * cA + sA;
        lB = lB * cB + sB;

#pragma unroll
        for (int nt = 0; nt < 16; nt++) {
            O[nt][0] *= cA; O[nt][1] *= cA;
            O[nt][2] *= cB; O[nt][3] *= cB;
        }
        __syncwarp();

        // ---- O += P @ V (16 x 128 per warp), 3xBF16 ----
#pragma unroll
        for (int kt = 0; kt < 4; kt++) {     // 16 keys per step
            const int ck = kt * 8 + lk;
            uint32_t pH[4], pL[4];
            pH[0] = Phi[rowA * PW + ck];     pL[0] = Plo[rowA * PW + ck];
            pH[1] = Phi[rowB * PW + ck];     pL[1] = Plo[rowB * PW + ck];
            pH[2] = Phi[rowA * PW + ck + 4]; pL[2] = Plo[rowA * PW + ck + 4];
            pH[3] = Phi[rowB * PW + ck + 4]; pL[3] = Plo[rowB * PW + ck + 4];
#pragma unroll
            for (int nt = 0; nt < 16; nt++) {
                const int vr = (nt * 8 + l4) * VW + ck;
                uint32_t vH[2], vL[2];
                vH[0] = Vhi[vr];     vH[1] = Vhi[vr + 4];
                vL[0] = Vlo[vr];     vL[1] = Vlo[vr + 4];
                mma_bf16(O[nt], pH, vH);
                mma_bf16(O[nt], pL, vH);
                mma_bf16(O[nt], pH, vL);
            }
        }
    }

    // ---- epilogue: O /= l, write [B*QL, NH*HD] ----
    float iA = 1.0f / lA, iB = 1.0f / lB;
    float* obase = o + ((size_t)(b * QL_ + q0 + rowA)) * (NH_ * HD_) + h * HD_;
#pragma unroll
    for (int nt = 0; nt < 16; nt++) {
        *(float2*)(obase + nt * 8 + 2 * lk) =
            make_float2(O[nt][0] * iA, O[nt][1] * iA);
        *(float2*)(obase + (size_t)8 * (NH_ * HD_) + nt * 8 + 2 * lk) =
            make_float2(O[nt][2] * iB, O[nt][3] * iB);
    }
}

// ---------------- launch ----------------
extern "C" void kernel_launch(void* const* d_in, const int* in_sizes, int n_in,
                              void* d_out, int out_size) {
    const float* noise = (const float*)d_in[0];
    const float* ctx   = (const float*)d_in[1];
    const float* cosT  = (const float*)d_in[2];
    const float* sinT  = (const float*)d_in[3];
    const float* Wq    = (const float*)d_in[4];
    const float* Wk    = (const float*)d_in[5];
    const float* Wv    = (const float*)d_in[6];
    const float* Wo    = (const float*)d_in[7];
    const float* qnw   = (const float*)d_in[8];
    const float* knw   = (const float*)d_in[9];
    float* out = (float*)d_out;

    float *qraw, *kraw, *vraw, *qn, *kn, *ao;
    cudaGetSymbolAddress((void**)&qraw, g_qraw);
    cudaGetSymbolAddress((void**)&kraw, g_kraw);
    cudaGetSymbolAddress((void**)&vraw, g_vraw);
    cudaGetSymbolAddress((void**)&qn,   g_qn);
    cudaGetSymbolAddress((void**)&kn,   g_kn);
    cudaGetSymbolAddress((void**)&ao,   g_ao);

    cudaFuncSetAttribute(flash_bf16_kernel, cudaFuncAttributeMaxDynamicSharedMemorySize,
                         FLASH_SMEM);

    // projections (tf32 tensor cores, 3xTF32 split)
    gemm_tf32_kernel<false><<<dim3(16, 32), 256>>>(noise, nullptr, nullptr, Wq, qraw,
                                                   B_ * QL_, NH_ * HD_);
    gemm_tf32_kernel<true><<<dim3(4, 128), 256>>>(nullptr, ctx, noise, Wk, kraw,
                                                  B_ * KL_, NKV_ * HD_);
    gemm_tf32_kernel<true><<<dim3(4, 128), 256>>>(nullptr, ctx, noise, Wv, vraw,
                                                  B_ * KL_, NKV_ * HD_);
    // norm + rope
    qnorm_rope_kernel<<<B_ * QL_ * NH_, 128>>>(qraw, cosT, sinT, qnw, qn);
    knorm_rope_kernel<<<B_ * KL_ * NKV_, 128>>>(kraw, cosT, sinT, knw, kn);
    // attention (bf16x3 tensor cores)
    flash_bf16_kernel<<<dim3(QL_ / 128, NH_, B_), 256, FLASH_SMEM>>>(qn, kn, vraw, ao);
    // output projection
    gemm_tf32_kernel<false><<<dim3(16, 32), 256>>>(ao, nullptr, nullptr, Wo, out,
                                                   B_ * QL_, NH_ * HD_);
}